// round 3
// baseline (speedup 1.0000x reference)
#include <cuda_runtime.h>
#include <cuda_bf16.h>
#include <stdint.h>

#define NN 4096
#define DD 256
#define BM 128
#define BN 128
#define SA 264          // bf16 elems per padded smem row (256 + 8) -> conflict-free frags
#define CSTRIDE 132     // float stride for staged C tile
#define NSPLIT 4
#define COLS_PER_BLOCK (NN / NSPLIT)   // 1024
#define NCHUNK (COLS_PER_BLOCK / BN)   // 8
#define INV_T 14.2857142857142857f

// scratch (no allocations allowed -> device globals)
__device__ __nv_bfloat16 g_fn[NN * DD];
__device__ float g_negP[NSPLIT * NN];
__device__ float g_pcsP[NSPLIT * NN];
__device__ float g_cntP[NSPLIT * NN];

// ---------------------------------------------------------------------------
// FFMA-only exp (MUFU EX2 at 0.5/cyc/SM would bottleneck: 16.8M exps)
// ---------------------------------------------------------------------------
__device__ __forceinline__ float fast_expf(float x) {
    float y = x * 1.4426950408889634f;      // log2(e)
    float n = rintf(y);
    float f = y - n;                        // f in [-0.5, 0.5]
    float p = 1.3333558146e-3f;             // Taylor 2^f, |rel err| < 2.5e-6
    p = fmaf(p, f, 9.6181291076e-3f);
    p = fmaf(p, f, 5.5504108664e-2f);
    p = fmaf(p, f, 2.4022650696e-1f);
    p = fmaf(p, f, 6.9314718056e-1f);
    p = fmaf(p, f, 1.0f);
    int ni = (int)n;                        // |ni| <= 21
    return p * __int_as_float((ni + 127) << 23);
}

// ---------------------------------------------------------------------------
// Kernel 1: row-normalize features, store bf16
// ---------------------------------------------------------------------------
__global__ void __launch_bounds__(256) normalize_kernel(const float* __restrict__ f) {
    int row  = blockIdx.x * 8 + (threadIdx.x >> 5);
    int lane = threadIdx.x & 31;
    const float4* src = (const float4*)(f + (size_t)row * DD);
    float4 v0 = src[lane * 2];
    float4 v1 = src[lane * 2 + 1];
    float ss = v0.x * v0.x;
    ss = fmaf(v0.y, v0.y, ss); ss = fmaf(v0.z, v0.z, ss); ss = fmaf(v0.w, v0.w, ss);
    ss = fmaf(v1.x, v1.x, ss); ss = fmaf(v1.y, v1.y, ss);
    ss = fmaf(v1.z, v1.z, ss); ss = fmaf(v1.w, v1.w, ss);
#pragma unroll
    for (int o = 16; o; o >>= 1) ss += __shfl_xor_sync(0xffffffffu, ss, o);
    float nrm = fmaxf(sqrtf(ss), 1e-8f);
    float s = 1.0f / nrm;
    __nv_bfloat162 h[4];
    h[0] = __floats2bfloat162_rn(v0.x * s, v0.y * s);
    h[1] = __floats2bfloat162_rn(v0.z * s, v0.w * s);
    h[2] = __floats2bfloat162_rn(v1.x * s, v1.y * s);
    h[3] = __floats2bfloat162_rn(v1.z * s, v1.w * s);
    *(uint4*)&g_fn[(size_t)row * DD + lane * 8] = *(uint4*)h;
}

// ---------------------------------------------------------------------------
// Kernel 2: fused bf16 MMA (cosim tile) + mask epilogue -> per-row partials
// grid (32 row-tiles, 4 col-splits), 256 threads, 135168 B dynamic smem
// ---------------------------------------------------------------------------
__global__ void __launch_bounds__(256, 1)
ssntx_main_kernel(const float* __restrict__ pmask, const float* __restrict__ nmask) {
    extern __shared__ unsigned char smem[];
    __nv_bfloat16* As = (__nv_bfloat16*)smem;                    // 128 x 264 bf16
    __nv_bfloat16* Bs = (__nv_bfloat16*)(smem + BM * SA * 2);    // 128 x 264 bf16
    float*         Cs = (float*)(smem + BM * SA * 2);            // aliases Bs (equal size)

    const int tid  = threadIdx.x;
    const int lane = tid & 31;
    const int warp = tid >> 5;
    const int g    = lane >> 2;      // group id 0..7
    const int tg   = lane & 3;       // thread-in-group 0..3
    const int wm   = warp >> 1;      // 0..3 -> 32-row band
    const int wn   = warp & 1;       // 0..1 -> 64-col band
    const int rowBase = blockIdx.x * BM;
    const int colBase = blockIdx.y * COLS_PER_BLOCK;

    // --- load A tile (reused across all 8 chunks) ---
#pragma unroll
    for (int i = 0; i < 16; i++) {
        int idx = i * 256 + tid;
        int r = idx >> 5, q = idx & 31;
        *(uint4*)&As[r * SA + q * 8] =
            *(const uint4*)&g_fn[(size_t)(rowBase + r) * DD + q * 8];
    }

    float negAcc = 0.f, pcsAcc = 0.f, cntAcc = 0.f;
    const int r_ep  = tid >> 1;            // epilogue row within tile
    const int cb_ep = (tid & 1) * 64;      // epilogue col segment
    const int ig    = rowBase + r_ep;      // global row

    for (int ch = 0; ch < NCHUNK; ch++) {
        const int jBase = colBase + ch * BN;

        __syncthreads();   // prior epilogue done reading Cs (aliases Bs)
        // --- load B tile ---
#pragma unroll
        for (int i = 0; i < 16; i++) {
            int idx = i * 256 + tid;
            int r = idx >> 5, q = idx & 31;
            *(uint4*)&Bs[r * SA + q * 8] =
                *(const uint4*)&g_fn[(size_t)(jBase + r) * DD + q * 8];
        }
        __syncthreads();

        // --- 128x128x256 via m16n8k16 bf16 MMA; warp tile 32x64 ---
        float acc[2][8][4];
#pragma unroll
        for (int mi = 0; mi < 2; mi++)
#pragma unroll
            for (int ni = 0; ni < 8; ni++)
#pragma unroll
                for (int k = 0; k < 4; k++) acc[mi][ni][k] = 0.f;

#pragma unroll 4
        for (int kb = 0; kb < DD; kb += 16) {
            uint32_t a[2][4];
#pragma unroll
            for (int mi = 0; mi < 2; mi++) {
                int row = wm * 32 + mi * 16 + g;
                const __nv_bfloat16* p0 = &As[row * SA + kb + tg * 2];
                const __nv_bfloat16* p1 = &As[(row + 8) * SA + kb + tg * 2];
                a[mi][0] = *(const uint32_t*)p0;
                a[mi][1] = *(const uint32_t*)p1;
                a[mi][2] = *(const uint32_t*)(p0 + 8);
                a[mi][3] = *(const uint32_t*)(p1 + 8);
            }
#pragma unroll
            for (int ni = 0; ni < 8; ni++) {
                int col = wn * 64 + ni * 8 + g;
                const __nv_bfloat16* pb = &Bs[col * SA + kb + tg * 2];
                uint32_t b0 = *(const uint32_t*)pb;
                uint32_t b1 = *(const uint32_t*)(pb + 8);
#pragma unroll
                for (int mi = 0; mi < 2; mi++) {
                    asm volatile(
                        "mma.sync.aligned.m16n8k16.row.col.f32.bf16.bf16.f32 "
                        "{%0,%1,%2,%3}, {%4,%5,%6,%7}, {%8,%9}, {%0,%1,%2,%3};"
                        : "+f"(acc[mi][ni][0]), "+f"(acc[mi][ni][1]),
                          "+f"(acc[mi][ni][2]), "+f"(acc[mi][ni][3])
                        : "r"(a[mi][0]), "r"(a[mi][1]), "r"(a[mi][2]), "r"(a[mi][3]),
                          "r"(b0), "r"(b1));
                }
            }
        }

        __syncthreads();   // all MMA reads of Bs complete before overwrite as Cs
        // --- stage C tile ---
#pragma unroll
        for (int mi = 0; mi < 2; mi++)
#pragma unroll
            for (int ni = 0; ni < 8; ni++) {
                int row = wm * 32 + mi * 16 + g;
                int col = wn * 64 + ni * 8 + tg * 2;
                *(float2*)&Cs[row * CSTRIDE + col] =
                    make_float2(acc[mi][ni][0], acc[mi][ni][1]);
                *(float2*)&Cs[(row + 8) * CSTRIDE + col] =
                    make_float2(acc[mi][ni][2], acc[mi][ni][3]);
            }
        __syncthreads();

        // --- epilogue: thread -> (row r_ep, 64-col segment), float4 streaming ---
        const float4* pm4 = (const float4*)(pmask + (size_t)ig * NN + jBase + cb_ep);
        const float4* nm4 = (const float4*)(nmask + (size_t)ig * NN + jBase + cb_ep);
        const float*  cR  = &Cs[r_ep * CSTRIDE + cb_ep];
#pragma unroll 4
        for (int q = 0; q < 16; q++) {
            float4 cv = *(const float4*)(cR + q * 4);
            float4 p4 = __ldcs(pm4 + q);   // read-once: evict-first
            float4 n4 = __ldcs(nm4 + q);
            int j0 = jBase + cb_ep + q * 4;
            {
                float c = cv.x * INV_T; float e = fast_expf(c);
                if (j0 + 0 != ig) { negAcc = fmaf(n4.x, e, negAcc); pcsAcc = fmaf(p4.x, c, pcsAcc); cntAcc += p4.x; }
            }
            {
                float c = cv.y * INV_T; float e = fast_expf(c);
                if (j0 + 1 != ig) { negAcc = fmaf(n4.y, e, negAcc); pcsAcc = fmaf(p4.y, c, pcsAcc); cntAcc += p4.y; }
            }
            {
                float c = cv.z * INV_T; float e = fast_expf(c);
                if (j0 + 2 != ig) { negAcc = fmaf(n4.z, e, negAcc); pcsAcc = fmaf(p4.z, c, pcsAcc); cntAcc += p4.z; }
            }
            {
                float c = cv.w * INV_T; float e = fast_expf(c);
                if (j0 + 3 != ig) { negAcc = fmaf(n4.w, e, negAcc); pcsAcc = fmaf(p4.w, c, pcsAcc); cntAcc += p4.w; }
            }
        }
    }

    // combine the 2 threads sharing a row, write per-split partials
    negAcc += __shfl_xor_sync(0xffffffffu, negAcc, 1);
    pcsAcc += __shfl_xor_sync(0xffffffffu, pcsAcc, 1);
    cntAcc += __shfl_xor_sync(0xffffffffu, cntAcc, 1);
    if ((tid & 1) == 0) {
        int s = blockIdx.y;
        g_negP[s * NN + ig] = negAcc;
        g_pcsP[s * NN + ig] = pcsAcc;
        g_cntP[s * NN + ig] = cntAcc;
    }
}

// ---------------------------------------------------------------------------
// Kernel 3: per-row loss terms + mean
// ---------------------------------------------------------------------------
__global__ void __launch_bounds__(256) finalize_kernel(float* __restrict__ out) {
    __shared__ float red[256];
    int tid = threadIdx.x;
    float local = 0.f;
    for (int i = tid; i < NN; i += 256) {
        float neg = 0.f, pcs = 0.f, cnt = 0.f;
#pragma unroll
        for (int s = 0; s < NSPLIT; s++) {
            neg += g_negP[s * NN + i];
            pcs += g_pcsP[s * NN + i];
            cnt += g_cntP[s * NN + i];
        }
        if (cnt > 0.f)
            local += (pcs - cnt * logf(fmaxf(neg, 1e-30f))) / cnt;
    }
    red[tid] = local;
    __syncthreads();
    for (int o = 128; o; o >>= 1) {
        if (tid < o) red[tid] += red[tid + o];
        __syncthreads();
    }
    if (tid == 0) out[0] = -red[0] / (float)NN;
}

// ---------------------------------------------------------------------------
extern "C" void kernel_launch(void* const* d_in, const int* in_sizes, int n_in,
                              void* d_out, int out_size) {
    const float* feat = (const float*)d_in[0];
    const float* pm   = (const float*)d_in[1];
    const float* nm   = (const float*)d_in[2];
    float* out = (float*)d_out;

    cudaFuncSetAttribute(ssntx_main_kernel,
                         cudaFuncAttributeMaxDynamicSharedMemorySize, 135168);

    normalize_kernel<<<NN / 8, 256>>>(feat);
    ssntx_main_kernel<<<dim3(NN / BM, NSPLIT), 256, 135168>>>(pm, nm);
    finalize_kernel<<<1, 256>>>(out);
}

// round 8
// speedup vs baseline: 1.1009x; 1.1009x over previous
#include <cuda_runtime.h>
#include <cuda_bf16.h>
#include <stdint.h>

#define NN 4096
#define DD 256
#define BM 128
#define BN 128
#define SA 264          // bf16 elems per padded smem row (256+8): conflict-free frag loads
#define CSTRIDE 132     // float stride for staged C tile (16B-aligned rows)
#define NCHUNKS 32      // 4096/128 column chunks
#define NROWT   32      // 4096/128 row tiles
#define NUNITS  (NCHUNKS * NROWT)   // 1024 work units
#define GRID 148
#define INV_T 14.285714285714286f

// scratch (no allocations allowed -> device globals)
__device__ __nv_bfloat16 g_fn[NN * DD];
__device__ float g_negP[NCHUNKS * NN];
__device__ float g_pcsP[NCHUNKS * NN];
__device__ float g_cntP[NCHUNKS * NN];
__device__ float g_rowLoss[NN];

// ---------------------------------------------------------------------------
// FFMA-only exp (MUFU EX2 at 0.5/cyc/SM would bottleneck: 16.8M exps)
// ---------------------------------------------------------------------------
__device__ __forceinline__ float fast_expf(float x) {
    float y = x * 1.4426950408889634f;
    float n = rintf(y);
    float f = y - n;
    float p = 1.3333558146e-3f;
    p = fmaf(p, f, 9.6181291076e-3f);
    p = fmaf(p, f, 5.5504108664e-2f);
    p = fmaf(p, f, 2.4022650696e-1f);
    p = fmaf(p, f, 6.9314718056e-1f);
    p = fmaf(p, f, 1.0f);
    int ni = (int)n;
    return p * __int_as_float((ni + 127) << 23);
}

__device__ __forceinline__ void cp16(void* s, const void* g) {
    uint32_t sa = (uint32_t)__cvta_generic_to_shared(s);
    asm volatile("cp.async.cg.shared.global [%0], [%1], 16;\n" :: "r"(sa), "l"(g));
}
__device__ __forceinline__ void cp_commit() {
    asm volatile("cp.async.commit_group;\n" ::: "memory");
}
__device__ __forceinline__ void cp_wait_all() {
    asm volatile("cp.async.wait_group 0;\n" ::: "memory");
}

// prefetch this thread's epilogue mask slice (256B per mask = 2 lines each) to L2
__device__ __forceinline__ void pf_masks(const float* pm, const float* nm,
                                         int rowBase, int jBase, int r_ep, int cb_ep) {
    size_t off = (size_t)(rowBase + r_ep) * NN + jBase + cb_ep;
    const char* p = (const char*)(pm + off);
    const char* n = (const char*)(nm + off);
    asm volatile("prefetch.global.L2 [%0];" :: "l"(p));
    asm volatile("prefetch.global.L2 [%0];" :: "l"(p + 128));
    asm volatile("prefetch.global.L2 [%0];" :: "l"(n));
    asm volatile("prefetch.global.L2 [%0];" :: "l"(n + 128));
}

// ---------------------------------------------------------------------------
// Kernel 1: row-normalize features, store bf16
// ---------------------------------------------------------------------------
__global__ void __launch_bounds__(256) normalize_kernel(const float* __restrict__ f) {
    int row  = blockIdx.x * 8 + (threadIdx.x >> 5);
    int lane = threadIdx.x & 31;
    const float4* src = (const float4*)(f + (size_t)row * DD);
    float4 v0 = src[lane * 2];
    float4 v1 = src[lane * 2 + 1];
    float ss = v0.x * v0.x;
    ss = fmaf(v0.y, v0.y, ss); ss = fmaf(v0.z, v0.z, ss); ss = fmaf(v0.w, v0.w, ss);
    ss = fmaf(v1.x, v1.x, ss); ss = fmaf(v1.y, v1.y, ss);
    ss = fmaf(v1.z, v1.z, ss); ss = fmaf(v1.w, v1.w, ss);
#pragma unroll
    for (int o = 16; o; o >>= 1) ss += __shfl_xor_sync(0xffffffffu, ss, o);
    float s = 1.0f / fmaxf(sqrtf(ss), 1e-8f);
    __nv_bfloat162 h[4];
    h[0] = __floats2bfloat162_rn(v0.x * s, v0.y * s);
    h[1] = __floats2bfloat162_rn(v0.z * s, v0.w * s);
    h[2] = __floats2bfloat162_rn(v1.x * s, v1.y * s);
    h[3] = __floats2bfloat162_rn(v1.z * s, v1.w * s);
    *(uint4*)&g_fn[(size_t)row * DD + lane * 8] = *(uint4*)h;
}

// ---------------------------------------------------------------------------
// Kernel 2: persistent fused MMA + epilogue over 1024 (rowTile, chunk) units.
// 148 CTAs x 256 threads, 202752 B dynamic smem (As | Bs | Cs, no aliasing).
// Pipeline per unit: wait B -> prefetch masks(u+1) -> MMA -> stage C -> sync
//                    -> cp.async B(u+1) -> epilogue(u) (masks are L2 hits)
// ---------------------------------------------------------------------------
__global__ void __launch_bounds__(256, 1)
ssntx_main_kernel(const float* __restrict__ pmask, const float* __restrict__ nmask) {
    extern __shared__ unsigned char smem[];
    __nv_bfloat16* As = (__nv_bfloat16*)smem;                        // 128 x 264 bf16
    __nv_bfloat16* Bs = (__nv_bfloat16*)(smem + BM * SA * 2);        // 128 x 264 bf16
    float*         Cs = (float*)(smem + 2 * BM * SA * 2);            // 128 x 132 f32

    const int tid  = threadIdx.x;
    const int lane = tid & 31;
    const int warp = tid >> 5;
    const int g    = lane >> 2;
    const int tg   = lane & 3;
    const int wm   = warp >> 1;
    const int wn   = warp & 1;
    const int r_ep  = tid >> 1;
    const int cb_ep = (tid & 1) * 64;

    const int uStart = (int)(((long long)blockIdx.x       * NUNITS) / GRID);
    const int uEnd   = (int)(((long long)(blockIdx.x + 1) * NUNITS) / GRID);

    // kick off B(uStart) + L2 prefetch of masks(uStart)
    {
        int rt = uStart >> 5, ch = uStart & 31;
        int jB = ch * BN;
#pragma unroll
        for (int i = 0; i < 16; i++) {
            int idx = i * 256 + tid;
            int r = idx >> 5, q = idx & 31;
            cp16(&Bs[r * SA + q * 8], &g_fn[(size_t)(jB + r) * DD + q * 8]);
        }
        cp_commit();
        pf_masks(pmask, nmask, rt * BM, jB, r_ep, cb_ep);
    }

    int curRT = -1;
    for (int u = uStart; u < uEnd; u++) {
        const int rt = u >> 5, ch = u & 31;
        const int rowBase = rt * BM, jBase = ch * BN;

        if (rt != curRT) {   // safe: all MMA reads of As drained at prior stage-C sync
            curRT = rt;
#pragma unroll
            for (int i = 0; i < 16; i++) {
                int idx = i * 256 + tid;
                int r = idx >> 5, q = idx & 31;
                cp16(&As[r * SA + q * 8], &g_fn[(size_t)(rowBase + r) * DD + q * 8]);
            }
            cp_commit();
        }

        cp_wait_all();       // A(u) + B(u) landed
        __syncthreads();     // also: all epilogue(u-1) reads of Cs done before stage-C below

        if (u + 1 < uEnd)    // overlap next unit's mask DRAM traffic with this MMA
            pf_masks(pmask, nmask, ((u + 1) >> 5) * BM, ((u + 1) & 31) * BN, r_ep, cb_ep);

        // --- 128x128x256 via m16n8k16 bf16 MMA; warp tile 32x64 ---
        float acc[2][8][4];
#pragma unroll
        for (int mi = 0; mi < 2; mi++)
#pragma unroll
            for (int ni = 0; ni < 8; ni++)
#pragma unroll
                for (int k = 0; k < 4; k++) acc[mi][ni][k] = 0.f;

#pragma unroll 4
        for (int kb = 0; kb < DD; kb += 16) {
            uint32_t a[2][4];
#pragma unroll
            for (int mi = 0; mi < 2; mi++) {
                int row = wm * 32 + mi * 16 + g;
                const __nv_bfloat16* p0 = &As[row * SA + kb + tg * 2];
                const __nv_bfloat16* p1 = &As[(row + 8) * SA + kb + tg * 2];
                a[mi][0] = *(const uint32_t*)p0;
                a[mi][1] = *(const uint32_t*)p1;
                a[mi][2] = *(const uint32_t*)(p0 + 8);
                a[mi][3] = *(const uint32_t*)(p1 + 8);
            }
#pragma unroll
            for (int ni = 0; ni < 8; ni++) {
                int col = wn * 64 + ni * 8 + g;
                const __nv_bfloat16* pb = &Bs[col * SA + kb + tg * 2];
                uint32_t b0 = *(const uint32_t*)pb;
                uint32_t b1 = *(const uint32_t*)(pb + 8);
#pragma unroll
                for (int mi = 0; mi < 2; mi++) {
                    asm volatile(
                        "mma.sync.aligned.m16n8k16.row.col.f32.bf16.bf16.f32 "
                        "{%0,%1,%2,%3}, {%4,%5,%6,%7}, {%8,%9}, {%0,%1,%2,%3};"
                        : "+f"(acc[mi][ni][0]), "+f"(acc[mi][ni][1]),
                          "+f"(acc[mi][ni][2]), "+f"(acc[mi][ni][3])
                        : "r"(a[mi][0]), "r"(a[mi][1]), "r"(a[mi][2]), "r"(a[mi][3]),
                          "r"(b0), "r"(b1));
                }
            }
        }

        // --- stage C (disjoint from Bs; no sync needed before) ---
#pragma unroll
        for (int mi = 0; mi < 2; mi++)
#pragma unroll
            for (int ni = 0; ni < 8; ni++) {
                int row = wm * 32 + mi * 16 + g;
                int col = wn * 64 + ni * 8 + tg * 2;
                *(float2*)&Cs[row * CSTRIDE + col] =
                    make_float2(acc[mi][ni][0], acc[mi][ni][1]);
                *(float2*)&Cs[(row + 8) * CSTRIDE + col] =
                    make_float2(acc[mi][ni][2], acc[mi][ni][3]);
            }
        __syncthreads();   // Cs ready; all MMA reads of Bs drained

        if (u + 1 < uEnd) {   // B(u+1) streams in under the epilogue
            int njB = ((u + 1) & 31) * BN;
#pragma unroll
            for (int i = 0; i < 16; i++) {
                int idx = i * 256 + tid;
                int r = idx >> 5, q = idx & 31;
                cp16(&Bs[r * SA + q * 8], &g_fn[(size_t)(njB + r) * DD + q * 8]);
            }
            cp_commit();
        }

        // --- epilogue: thread -> (row r_ep, 64-col segment); masks are L2 hits ---
        const int ig = rowBase + r_ep;
        float negAcc = 0.f, pcsAcc = 0.f, cntAcc = 0.f;
        const float4* pm4 = (const float4*)(pmask + (size_t)ig * NN + jBase + cb_ep);
        const float4* nm4 = (const float4*)(nmask + (size_t)ig * NN + jBase + cb_ep);
        const float*  cR  = &Cs[r_ep * CSTRIDE + cb_ep];
#pragma unroll 4
        for (int q = 0; q < 16; q++) {
            float4 cv = *(const float4*)(cR + q * 4);
            float4 p4 = __ldcs(pm4 + q);
            float4 n4 = __ldcs(nm4 + q);
            int j0 = jBase + cb_ep + q * 4;
            {
                float c = cv.x * INV_T; float e = fast_expf(c);
                if (j0 + 0 != ig) { negAcc = fmaf(n4.x, e, negAcc); pcsAcc = fmaf(p4.x, c, pcsAcc); cntAcc += p4.x; }
            }
            {
                float c = cv.y * INV_T; float e = fast_expf(c);
                if (j0 + 1 != ig) { negAcc = fmaf(n4.y, e, negAcc); pcsAcc = fmaf(p4.y, c, pcsAcc); cntAcc += p4.y; }
            }
            {
                float c = cv.z * INV_T; float e = fast_expf(c);
                if (j0 + 2 != ig) { negAcc = fmaf(n4.z, e, negAcc); pcsAcc = fmaf(p4.z, c, pcsAcc); cntAcc += p4.z; }
            }
            {
                float c = cv.w * INV_T; float e = fast_expf(c);
                if (j0 + 3 != ig) { negAcc = fmaf(n4.w, e, negAcc); pcsAcc = fmaf(p4.w, c, pcsAcc); cntAcc += p4.w; }
            }
        }

        // combine the 2 threads sharing a row; (chunk,row) slot written exactly once
        negAcc += __shfl_xor_sync(0xffffffffu, negAcc, 1);
        pcsAcc += __shfl_xor_sync(0xffffffffu, pcsAcc, 1);
        cntAcc += __shfl_xor_sync(0xffffffffu, cntAcc, 1);
        if ((tid & 1) == 0) {
            g_negP[ch * NN + ig] = negAcc;
            g_pcsP[ch * NN + ig] = pcsAcc;
            g_cntP[ch * NN + ig] = cntAcc;
        }
    }
}

// ---------------------------------------------------------------------------
// Kernel 3a: per-row loss terms (4096 threads)
// ---------------------------------------------------------------------------
__global__ void __launch_bounds__(256) rowloss_kernel() {
    int i = blockIdx.x * 256 + threadIdx.x;
    float neg = 0.f, pcs = 0.f, cnt = 0.f;
#pragma unroll 8
    for (int s = 0; s < NCHUNKS; s++) {
        neg += g_negP[s * NN + i];
        pcs += g_pcsP[s * NN + i];
        cnt += g_cntP[s * NN + i];
    }
    float t = 0.f;
    if (cnt > 0.f) t = (pcs - cnt * logf(fmaxf(neg, 1e-30f))) / cnt;
    g_rowLoss[i] = t;
}

// ---------------------------------------------------------------------------
// Kernel 3b: mean -> loss
// ---------------------------------------------------------------------------
__global__ void __launch_bounds__(256) reduce_kernel(float* __restrict__ out) {
    __shared__ float red[256];
    int tid = threadIdx.x;
    float l = 0.f;
    for (int i = tid; i < NN; i += 256) l += g_rowLoss[i];
    red[tid] = l;
    __syncthreads();
    for (int o = 128; o; o >>= 1) {
        if (tid < o) red[tid] += red[tid + o];
        __syncthreads();
    }
    if (tid == 0) out[0] = -red[0] / (float)NN;
}

// ---------------------------------------------------------------------------
extern "C" void kernel_launch(void* const* d_in, const int* in_sizes, int n_in,
                              void* d_out, int out_size) {
    const float* feat = (const float*)d_in[0];
    const float* pm   = (const float*)d_in[1];
    const float* nm   = (const float*)d_in[2];
    float* out = (float*)d_out;

    cudaFuncSetAttribute(ssntx_main_kernel,
                         cudaFuncAttributeMaxDynamicSharedMemorySize, 202752);

    normalize_kernel<<<NN / 8, 256>>>(feat);
    ssntx_main_kernel<<<GRID, 256, 202752>>>(pm, nm);
    rowloss_kernel<<<NN / 256, 256>>>();
    reduce_kernel<<<1, 256>>>(out);
}

// round 10
// speedup vs baseline: 1.3859x; 1.2589x over previous
#include <cuda_runtime.h>
#include <cuda_bf16.h>
#include <stdint.h>

#define NN 4096
#define DD 256
#define BM 128
#define BN 128
#define SA 264          // bf16 elems per padded smem row (256+8): conflict-free frag loads
#define NCHUNKS 32
#define NROWT   32
#define NUNITS  (NCHUNKS * NROWT)
#define GRID 148
#define INV_T 14.285714285714286f

// scratch (no allocations allowed -> device globals)
__device__ __nv_bfloat16 g_fn[NN * DD];
__device__ uint32_t g_pmBits[NN * 128];   // 4096 bits per row = 128 u32
__device__ uint32_t g_nmBits[NN * 128];
__device__ float g_negP[NCHUNKS * 2 * NN];
__device__ float g_pcsP[NCHUNKS * 2 * NN];
__device__ float g_cntP[NCHUNKS * 2 * NN];
__device__ float g_blockSum[16];

// ---------------------------------------------------------------------------
// FFMA-only exp (16.8M exps; MUFU EX2 would bottleneck)
// ---------------------------------------------------------------------------
__device__ __forceinline__ float fast_expf(float x) {
    float y = x * 1.4426950408889634f;
    float n = rintf(y);
    float f = y - n;
    float p = 1.3333558146e-3f;
    p = fmaf(p, f, 9.6181291076e-3f);
    p = fmaf(p, f, 5.5504108664e-2f);
    p = fmaf(p, f, 2.4022650696e-1f);
    p = fmaf(p, f, 6.9314718056e-1f);
    p = fmaf(p, f, 1.0f);
    int ni = (int)n;
    return p * __int_as_float((ni + 127) << 23);
}

__device__ __forceinline__ void cp16(void* s, const void* g) {
    uint32_t sa = (uint32_t)__cvta_generic_to_shared(s);
    asm volatile("cp.async.cg.shared.global [%0], [%1], 16;\n" :: "r"(sa), "l"(g));
}
__device__ __forceinline__ void cp_commit()  { asm volatile("cp.async.commit_group;\n" ::: "memory"); }
__device__ __forceinline__ void cp_wait_all(){ asm volatile("cp.async.wait_group 0;\n" ::: "memory"); }

// ---------------------------------------------------------------------------
// Kernel 1: fused prep. Blocks 0..511: row-normalize -> bf16 g_fn.
//           Blocks 512..1535: pack masks to bits (4 rows/block, ballot).
// ---------------------------------------------------------------------------
__global__ void __launch_bounds__(256)
prep_kernel(const float* __restrict__ f,
            const float* __restrict__ pmask, const float* __restrict__ nmask) {
    const int tid  = threadIdx.x;
    const int lane = tid & 31;
    const int warp = tid >> 5;

    if (blockIdx.x < 512) {
        int row = blockIdx.x * 8 + warp;
        const float4* src = (const float4*)(f + (size_t)row * DD);
        float4 v0 = src[lane * 2];
        float4 v1 = src[lane * 2 + 1];
        float ss = v0.x * v0.x;
        ss = fmaf(v0.y, v0.y, ss); ss = fmaf(v0.z, v0.z, ss); ss = fmaf(v0.w, v0.w, ss);
        ss = fmaf(v1.x, v1.x, ss); ss = fmaf(v1.y, v1.y, ss);
        ss = fmaf(v1.z, v1.z, ss); ss = fmaf(v1.w, v1.w, ss);
#pragma unroll
        for (int o = 16; o; o >>= 1) ss += __shfl_xor_sync(0xffffffffu, ss, o);
        float s = 1.0f / fmaxf(sqrtf(ss), 1e-8f);
        __nv_bfloat162 h[4];
        h[0] = __floats2bfloat162_rn(v0.x * s, v0.y * s);
        h[1] = __floats2bfloat162_rn(v0.z * s, v0.w * s);
        h[2] = __floats2bfloat162_rn(v1.x * s, v1.y * s);
        h[3] = __floats2bfloat162_rn(v1.z * s, v1.w * s);
        *(uint4*)&g_fn[(size_t)row * DD + lane * 8] = *(uint4*)h;
    } else {
        int p = blockIdx.x - 512;                 // 0..1023, 4 rows each
#pragma unroll
        for (int r = 0; r < 4; r++) {
            int row = p * 4 + r;
            const float* pmRow = pmask + (size_t)row * NN;
            const float* nmRow = nmask + (size_t)row * NN;
            // warp w covers cols [w*512, w*512+512), 16 ballot rounds
#pragma unroll 4
            for (int i = 0; i < 16; i++) {
                int col = warp * 512 + i * 32 + lane;
                uint32_t pb = __ballot_sync(0xffffffffu, pmRow[col] != 0.f);
                uint32_t nb = __ballot_sync(0xffffffffu, nmRow[col] != 0.f);
                if (lane == 0) {
                    g_pmBits[row * 128 + (warp * 512 + i * 32) / 32] = pb;
                    g_nmBits[row * 128 + (warp * 512 + i * 32) / 32] = nb;
                }
            }
        }
    }
}

// ---------------------------------------------------------------------------
// Kernel 2: persistent mma.sync GEMM + in-register bitmask epilogue.
// 148 CTAs x 256 threads. smem = A | B0 | B1 (202752 B), no C staging.
// Per unit: wait cp -> sync -> issue B(u+1) cp -> MMA -> [rt-cross: sync + A cp]
//           -> epilogue on fragments (bits, ~4KB/unit mask traffic).
// ---------------------------------------------------------------------------
__global__ void __launch_bounds__(256, 1)
ssntx_main_kernel() {
    extern __shared__ unsigned char smem[];
    __nv_bfloat16* As = (__nv_bfloat16*)smem;                        // 128 x 264
    __nv_bfloat16* B0 = (__nv_bfloat16*)(smem + BM * SA * 2);
    __nv_bfloat16* B1 = (__nv_bfloat16*)(smem + 2 * BM * SA * 2);

    const int tid  = threadIdx.x;
    const int lane = tid & 31;
    const int warp = tid >> 5;
    const int g    = lane >> 2;      // 0..7
    const int tg   = lane & 3;       // 0..3
    const int wm   = warp >> 1;      // 32-row band
    const int wn   = warp & 1;       // 64-col band

    const int uStart = (int)(((long long)blockIdx.x       * NUNITS) / GRID);
    const int uEnd   = (int)(((long long)(blockIdx.x + 1) * NUNITS) / GRID);

    // prologue: A(rt0) + B(u0) -> buf0
    {
        int rt0 = uStart >> 5, ch0 = uStart & 31;
#pragma unroll
        for (int i = 0; i < 16; i++) {
            int idx = i * 256 + tid;
            int r = idx >> 5, q = idx & 31;
            cp16(&As[r * SA + q * 8], &g_fn[(size_t)(rt0 * BM + r) * DD + q * 8]);
            cp16(&B0[r * SA + q * 8], &g_fn[(size_t)(ch0 * BN + r) * DD + q * 8]);
        }
        cp_commit();
    }

    const uint64_t tgmask = 0x0303030303030303ULL << (tg * 2);

    for (int u = uStart; u < uEnd; u++) {
        const int rt = u >> 5, ch = u & 31;
        const int rowBase = rt * BM, jBase = ch * BN;
        __nv_bfloat16* Bc = ((u - uStart) & 1) ? B1 : B0;
        __nv_bfloat16* Bn = ((u - uStart) & 1) ? B0 : B1;

        cp_wait_all();
        __syncthreads();               // A + B(u) visible to all warps

        const bool hasNext = (u + 1 < uEnd);
        const int  nrt = (u + 1) >> 5, nch = (u + 1) & 31;

        if (hasNext && nrt == rt) {    // B(u+1) streams during MMA + epilogue
#pragma unroll
            for (int i = 0; i < 16; i++) {
                int idx = i * 256 + tid;
                int r = idx >> 5, q = idx & 31;
                cp16(&Bn[r * SA + q * 8], &g_fn[(size_t)(nch * BN + r) * DD + q * 8]);
            }
            cp_commit();
        }

        // --- 128x128x256 via m16n8k16 bf16 MMA; warp tile 32x64 ---
        float acc[2][8][4];
#pragma unroll
        for (int mi = 0; mi < 2; mi++)
#pragma unroll
            for (int ni = 0; ni < 8; ni++)
#pragma unroll
                for (int k = 0; k < 4; k++) acc[mi][ni][k] = 0.f;

#pragma unroll 4
        for (int kb = 0; kb < DD; kb += 16) {
            uint32_t a[2][4];
#pragma unroll
            for (int mi = 0; mi < 2; mi++) {
                int row = wm * 32 + mi * 16 + g;
                const __nv_bfloat16* p0 = &As[row * SA + kb + tg * 2];
                const __nv_bfloat16* p1 = &As[(row + 8) * SA + kb + tg * 2];
                a[mi][0] = *(const uint32_t*)p0;
                a[mi][1] = *(const uint32_t*)p1;
                a[mi][2] = *(const uint32_t*)(p0 + 8);
                a[mi][3] = *(const uint32_t*)(p1 + 8);
            }
#pragma unroll
            for (int ni = 0; ni < 8; ni++) {
                int col = wn * 64 + ni * 8 + g;
                const __nv_bfloat16* pb = &Bc[col * SA + kb + tg * 2];
                uint32_t b0 = *(const uint32_t*)pb;
                uint32_t b1 = *(const uint32_t*)(pb + 8);
#pragma unroll
                for (int mi = 0; mi < 2; mi++) {
                    asm volatile(
                        "mma.sync.aligned.m16n8k16.row.col.f32.bf16.bf16.f32 "
                        "{%0,%1,%2,%3}, {%4,%5,%6,%7}, {%8,%9}, {%0,%1,%2,%3};"
                        : "+f"(acc[mi][ni][0]), "+f"(acc[mi][ni][1]),
                          "+f"(acc[mi][ni][2]), "+f"(acc[mi][ni][3])
                        : "r"(a[mi][0]), "r"(a[mi][1]), "r"(a[mi][2]), "r"(a[mi][3]),
                          "r"(b0), "r"(b1));
                }
            }
        }

        if (hasNext && nrt != rt) {    // row-tile crossing: reload A (+B) safely
            __syncthreads();           // uniform: all warps done reading As
#pragma unroll
            for (int i = 0; i < 16; i++) {
                int idx = i * 256 + tid;
                int r = idx >> 5, q = idx & 31;
                cp16(&As[r * SA + q * 8], &g_fn[(size_t)(nrt * BM + r) * DD + q * 8]);
                cp16(&Bn[r * SA + q * 8], &g_fn[(size_t)(nch * BN + r) * DD + q * 8]);
            }
            cp_commit();
        }

        // --- epilogue on fragments: 4 row-contexts (mi, h), 16 cols each ---
        const int colSeg = jBase + wn * 64;
        const int widx0  = (jBase >> 5) + wn * 2;
#pragma unroll
        for (int mi = 0; mi < 2; mi++) {
#pragma unroll
            for (int h = 0; h < 2; h++) {
                int r  = wm * 32 + mi * 16 + h * 8 + g;
                int ig = rowBase + r;
                int wi = ig * 128 + widx0;
                uint64_t pm64 = (uint64_t)g_pmBits[wi] | ((uint64_t)g_pmBits[wi + 1] << 32);
                uint64_t nm64 = (uint64_t)g_nmBits[wi] | ((uint64_t)g_nmBits[wi + 1] << 32);
                int d = ig - colSeg;
                if ((unsigned)d < 64u) {
                    uint64_t clr = ~(1ULL << d);
                    pm64 &= clr; nm64 &= clr;
                }
                float cnt = (float)__popcll(pm64 & tgmask);
                float neg = 0.f, pcs = 0.f;
#pragma unroll
                for (int ni = 0; ni < 8; ni++) {
                    int o = ni * 8 + tg * 2;
                    float c0 = acc[mi][ni][h * 2 + 0] * INV_T;
                    float c1 = acc[mi][ni][h * 2 + 1] * INV_T;
                    float e0 = fast_expf(c0);
                    float e1 = fast_expf(c1);
                    if ((nm64 >> o) & 1)       neg += e0;
                    if ((nm64 >> (o + 1)) & 1) neg += e1;
                    if ((pm64 >> o) & 1)       pcs += c0;
                    if ((pm64 >> (o + 1)) & 1) pcs += c1;
                }
                // reduce across the 4 tg lanes sharing these rows/cols
                neg += __shfl_xor_sync(0xffffffffu, neg, 1);
                pcs += __shfl_xor_sync(0xffffffffu, pcs, 1);
                cnt += __shfl_xor_sync(0xffffffffu, cnt, 1);
                neg += __shfl_xor_sync(0xffffffffu, neg, 2);
                pcs += __shfl_xor_sync(0xffffffffu, pcs, 2);
                cnt += __shfl_xor_sync(0xffffffffu, cnt, 2);
                if (tg == 0) {
                    int slot = (ch * 2 + wn) * NN + ig;
                    g_negP[slot] = neg;
                    g_pcsP[slot] = pcs;
                    g_cntP[slot] = cnt;
                }
            }
        }
    }
}

// ---------------------------------------------------------------------------
// Kernel 3a: per-row loss terms + in-block reduce -> 16 partials
// ---------------------------------------------------------------------------
__global__ void __launch_bounds__(256) rowloss_kernel() {
    __shared__ float red[256];
    int i = blockIdx.x * 256 + threadIdx.x;
    float neg = 0.f, pcs = 0.f, cnt = 0.f;
#pragma unroll 8
    for (int s = 0; s < NCHUNKS * 2; s++) {
        neg += g_negP[s * NN + i];
        pcs += g_pcsP[s * NN + i];
        cnt += g_cntP[s * NN + i];
    }
    float t = 0.f;
    if (cnt > 0.f) t = (pcs - cnt * logf(fmaxf(neg, 1e-30f))) / cnt;
    red[threadIdx.x] = t;
    __syncthreads();
    for (int o = 128; o; o >>= 1) {
        if (threadIdx.x < o) red[threadIdx.x] += red[threadIdx.x + o];
        __syncthreads();
    }
    if (threadIdx.x == 0) g_blockSum[blockIdx.x] = red[0];
}

// ---------------------------------------------------------------------------
// Kernel 3b: sum 16 partials -> loss
// ---------------------------------------------------------------------------
__global__ void reduce_kernel(float* __restrict__ out) {
    int lane = threadIdx.x;
    float v = (lane < 16) ? g_blockSum[lane] : 0.f;
#pragma unroll
    for (int o = 8; o; o >>= 1) v += __shfl_xor_sync(0xffffffffu, v, o);
    if (lane == 0) out[0] = -v / (float)NN;
}

// ---------------------------------------------------------------------------
extern "C" void kernel_launch(void* const* d_in, const int* in_sizes, int n_in,
                              void* d_out, int out_size) {
    const float* feat = (const float*)d_in[0];
    const float* pm   = (const float*)d_in[1];
    const float* nm   = (const float*)d_in[2];
    float* out = (float*)d_out;

    cudaFuncSetAttribute(ssntx_main_kernel,
                         cudaFuncAttributeMaxDynamicSharedMemorySize, 202752);

    prep_kernel<<<1536, 256>>>(feat, pm, nm);
    ssntx_main_kernel<<<GRID, 256, 202752>>>();
    rowloss_kernel<<<NN / 256, 256>>>();
    reduce_kernel<<<1, 32>>>(out);
}